// round 1
// baseline (speedup 1.0000x reference)
#include <cuda_runtime.h>
#include <cstdint>
#include <cstddef>

#define RR 8
#define NN 300000
#define DD 128
#define AA 64
#define TILE_M 128
#define HSTRIDE 132   // 128 + 4 pad -> conflict-free A-fragment LDS
#define WSTRIDE 72    // 64 + 8 pad  -> conflict-free B-fragment LDS

// scratch: scores[r][n]
__device__ float g_scores[RR * (size_t)NN];

__device__ __forceinline__ unsigned f2tf32(float x) {
    unsigned r;
    asm("cvt.rna.tf32.f32 %0, %1;" : "=r"(r) : "f"(x));
    return r;
}

__device__ __forceinline__ float fast_sigmoid(float x) {
    // 1 / (1 + 2^(-x*log2(e)))
    float e;
    asm("ex2.approx.f32 %0, %1;" : "=f"(e) : "f"(-1.4426950408889634f * x));
    float r;
    asm("rcp.approx.f32 %0, %1;" : "=f"(r) : "f"(1.0f + e));
    return r;
}

__device__ __forceinline__ void mma_tf32_16n8k8(float c[4],
                                                const unsigned a[4],
                                                unsigned b0, unsigned b1) {
    asm volatile(
        "mma.sync.aligned.m16n8k8.row.col.f32.tf32.tf32.f32 "
        "{%0,%1,%2,%3}, {%4,%5,%6,%7}, {%8,%9}, {%0,%1,%2,%3};"
        : "+f"(c[0]), "+f"(c[1]), "+f"(c[2]), "+f"(c[3])
        : "r"(a[0]), "r"(a[1]), "r"(a[2]), "r"(a[3]), "r"(b0), "r"(b1));
}

// Kernel 1: per (relation, node-tile): scores = sigmoid(h @ W1) @ w2
__global__ void __launch_bounds__(256, 2)
score_kernel(const float* __restrict__ h,
             const float* __restrict__ w1,
             const float* __restrict__ w2) {
    extern __shared__ float smem[];
    float* sh_h   = smem;                         // TILE_M * HSTRIDE
    float* sh_w1  = sh_h + TILE_M * HSTRIDE;      // DD * WSTRIDE
    float* sh_w2  = sh_w1 + DD * WSTRIDE;         // AA
    float* sh_prt = sh_w2 + AA;                   // 2 * TILE_M

    const int r = blockIdx.y;
    const long node0 = (long)blockIdx.x * TILE_M;
    const int tid = threadIdx.x;

    // ---- stage h tile (convert to tf32) ----
    const float4* hg = (const float4*)(h + (size_t)r * NN * DD);
    #pragma unroll
    for (int i = 0; i < 16; i++) {
        int idx = tid + i * 256;
        int row = idx >> 5, c4 = idx & 31;
        float4 v = make_float4(0.f, 0.f, 0.f, 0.f);
        long node = node0 + row;
        if (node < NN) v = hg[(size_t)node * 32 + c4];
        unsigned* dst = (unsigned*)&sh_h[row * HSTRIDE + c4 * 4];
        dst[0] = f2tf32(v.x); dst[1] = f2tf32(v.y);
        dst[2] = f2tf32(v.z); dst[3] = f2tf32(v.w);
    }
    // ---- stage W1 (D x A, row-major) ----
    const float4* wg = (const float4*)(w1 + (size_t)r * DD * AA);
    #pragma unroll
    for (int i = 0; i < 8; i++) {
        int idx = tid + i * 256;
        int row = idx >> 4, c4 = idx & 15;
        float4 v = wg[idx];
        unsigned* dst = (unsigned*)&sh_w1[row * WSTRIDE + c4 * 4];
        dst[0] = f2tf32(v.x); dst[1] = f2tf32(v.y);
        dst[2] = f2tf32(v.z); dst[3] = f2tf32(v.w);
    }
    if (tid < AA) sh_w2[tid] = w2[r * AA + tid];
    __syncthreads();

    // ---- MMA: each warp: 2 m-tiles (32 rows) x 4 n-tiles (32 cols) ----
    const int w = tid >> 5, lane = tid & 31;
    const int g = lane >> 2, tg = lane & 3;
    const int m0 = (w & 3) * 32;
    const int nh = w >> 2;                 // n-half: 0 or 1

    float acc[2][4][4];
    #pragma unroll
    for (int mt = 0; mt < 2; mt++)
        #pragma unroll
        for (int n = 0; n < 4; n++)
            #pragma unroll
            for (int q = 0; q < 4; q++) acc[mt][n][q] = 0.f;

    const unsigned* hh = (const unsigned*)sh_h;
    const unsigned* ww = (const unsigned*)sh_w1;

    for (int kc = 0; kc < 4; kc++) {       // K chunks of 32
        unsigned a[2][4][4];
        #pragma unroll
        for (int mt = 0; mt < 2; mt++)
            #pragma unroll
            for (int kt = 0; kt < 4; kt++) {
                int row = m0 + mt * 16 + g;
                int col = kc * 32 + kt * 8 + tg;
                a[mt][kt][0] = hh[row * HSTRIDE + col];
                a[mt][kt][1] = hh[(row + 8) * HSTRIDE + col];
                a[mt][kt][2] = hh[row * HSTRIDE + col + 4];
                a[mt][kt][3] = hh[(row + 8) * HSTRIDE + col + 4];
            }
        #pragma unroll
        for (int n = 0; n < 4; n++)
            #pragma unroll
            for (int kt = 0; kt < 4; kt++) {
                int k = kc * 32 + kt * 8;
                int nb = nh * 32 + n * 8;
                unsigned b0 = ww[(k + tg) * WSTRIDE + nb + g];
                unsigned b1 = ww[(k + tg + 4) * WSTRIDE + nb + g];
                #pragma unroll
                for (int mt = 0; mt < 2; mt++)
                    mma_tf32_16n8k8(acc[mt][n], a[mt][kt], b0, b1);
            }
    }

    // ---- epilogue: sigmoid, dot with w2, reduce to per-node score ----
    float slo[2] = {0.f, 0.f}, shi[2] = {0.f, 0.f};
    #pragma unroll
    for (int mt = 0; mt < 2; mt++)
        #pragma unroll
        for (int n = 0; n < 4; n++) {
            int cb = nh * 32 + n * 8 + 2 * tg;
            float wa = sh_w2[cb], wb = sh_w2[cb + 1];
            slo[mt] += fast_sigmoid(acc[mt][n][0]) * wa + fast_sigmoid(acc[mt][n][1]) * wb;
            shi[mt] += fast_sigmoid(acc[mt][n][2]) * wa + fast_sigmoid(acc[mt][n][3]) * wb;
        }
    #pragma unroll
    for (int o = 1; o < 4; o <<= 1) {
        slo[0] += __shfl_xor_sync(0xffffffffu, slo[0], o);
        slo[1] += __shfl_xor_sync(0xffffffffu, slo[1], o);
        shi[0] += __shfl_xor_sync(0xffffffffu, shi[0], o);
        shi[1] += __shfl_xor_sync(0xffffffffu, shi[1], o);
    }
    if (tg == 0) {
        #pragma unroll
        for (int mt = 0; mt < 2; mt++) {
            sh_prt[nh * TILE_M + m0 + mt * 16 + g]     = slo[mt];
            sh_prt[nh * TILE_M + m0 + mt * 16 + g + 8] = shi[mt];
        }
    }
    __syncthreads();
    if (tid < TILE_M) {
        long node = node0 + tid;
        if (node < NN)
            g_scores[(size_t)r * NN + node] = sh_prt[tid] + sh_prt[TILE_M + tid];
    }
}

// Kernel 2: softmax over relations + weighted sum. One warp per node.
__global__ void __launch_bounds__(256)
combine_kernel(const float* __restrict__ h, float* __restrict__ out) {
    const int warp = threadIdx.x >> 5, lane = threadIdx.x & 31;
    const long node = (long)blockIdx.x * 8 + warp;
    if (node >= NN) return;

    float s = -1e30f;
    if (lane < RR) s = g_scores[(size_t)lane * NN + node];
    float m = s;
    #pragma unroll
    for (int o = 4; o; o >>= 1) m = fmaxf(m, __shfl_xor_sync(0xffffffffu, m, o));
    float e = (lane < RR) ? __expf(s - m) : 0.f;
    float sum = e;
    #pragma unroll
    for (int o = 4; o; o >>= 1) sum += __shfl_xor_sync(0xffffffffu, sum, o);
    float attn = e / sum;

    float a[RR];
    #pragma unroll
    for (int rr = 0; rr < RR; rr++) a[rr] = __shfl_sync(0xffffffffu, attn, rr);

    const float4* hp = (const float4*)h;
    float4 o4 = make_float4(0.f, 0.f, 0.f, 0.f);
    #pragma unroll
    for (int rr = 0; rr < RR; rr++) {
        float4 v = hp[((size_t)rr * NN + node) * 32 + lane];
        o4.x += a[rr] * v.x; o4.y += a[rr] * v.y;
        o4.z += a[rr] * v.z; o4.w += a[rr] * v.w;
    }
    ((float4*)out)[(size_t)node * 32 + lane] = o4;
}

extern "C" void kernel_launch(void* const* d_in, const int* in_sizes, int n_in,
                              void* d_out, int out_size) {
    const float* h  = (const float*)d_in[0];
    const float* w1 = (const float*)d_in[1];
    const float* w2 = (const float*)d_in[2];
    float* out = (float*)d_out;

    const int smem_bytes = (TILE_M * HSTRIDE + DD * WSTRIDE + AA + 2 * TILE_M) * 4;
    cudaFuncSetAttribute(score_kernel,
                         cudaFuncAttributeMaxDynamicSharedMemorySize, smem_bytes);

    dim3 grid1((NN + TILE_M - 1) / TILE_M, RR);
    score_kernel<<<grid1, 256, smem_bytes>>>(h, w1, w2);

    int grid2 = (NN + 7) / 8;
    combine_kernel<<<grid2, 256>>>(h, out);
}